// round 2
// baseline (speedup 1.0000x reference)
#include <cuda_runtime.h>
#include <math.h>
#include <stdint.h>

// ---------------- problem constants ----------------
#define BATCH   8
#define CIN     512
#define HH      50
#define WW      76
#define HW      3800            // 50*76
#define NPIX    30400           // BATCH*HW
#define KDIM    4608            // 512*9
#define OC      512
#define ANCH    34200           // HW*9
#define SORTN   65536
#define PRE_NMS 6000
#define POST_NMS 300
#define NMS_TH  0.7f

// output layout (flattened concat of reference outputs, fp32)
#define OUT_LOC 0
#define OUT_SCR 1094400
#define OUT_ROI 1641600
#define OUT_ANC 1651200

// ---------------- device scratch (static, allocation-free) ----------------
__device__ float              g_col [(size_t)KDIM * NPIX + 128]; // im2col matrix (+pad for OOB float4)
__device__ float              g_feat[(size_t)OC * NPIX];          // conv1 output (relu), [c][n]
__device__ float              g_fg  [BATCH * ANCH];               // softmax fg prob
__device__ float4             g_boxes[BATCH * ANCH];              // clipped proposals
__device__ float4             g_anchor4[ANCH];
__device__ unsigned long long g_keys[BATCH * SORTN];              // sort keys

// ---------------- im2col ----------------
__global__ void im2col_k(const float* __restrict__ x)
{
    int n = blockIdx.x * 128 + threadIdx.x;   // pixel id (b,y,x)
    int k = blockIdx.y;                       // (c,ky,kx)
    if (n >= NPIX) return;
    int c  = k / 9;
    int r  = k - c * 9;
    int ky = r / 3, kx = r - (r / 3) * 3;
    int b  = n / HW;
    int p  = n - b * HW;
    int y  = p / WW;
    int xq = p - y * WW;
    int yy = y + ky - 1, xx = xq + kx - 1;
    float v = 0.f;
    if (yy >= 0 && yy < HH && xx >= 0 && xx < WW)
        v = x[(((size_t)b * CIN + c) * HH + yy) * WW + xx];
    g_col[(size_t)k * NPIX + n] = v;
}

// ---------------- SGEMM 512 x 30400 x 4608, bias + relu ----------------
// C[m][n] = relu(sum_k A[m][k]*B[k][n] + bias[m]);  A row-major (lda=K), B row-major (ldb=N)
__global__ __launch_bounds__(256, 2) void sgemm_bias_relu_k(
    const float* __restrict__ A, const float* __restrict__ bias)
{
    const int M = OC, N = NPIX, K = KDIM;
    __shared__ float As[2][8][128];
    __shared__ float Bs[2][8][128];

    const int tid  = threadIdx.x;
    const int m0   = blockIdx.y * 128;
    const int n0   = blockIdx.x * 128;
    const int tx   = tid & 15;        // 0..15  -> column group
    const int ty   = tid >> 4;        // 0..15  -> row group
    const int arow = tid >> 1;        // 0..127
    const int acol = (tid & 1) * 4;   // 0 or 4
    const int brow = tid >> 5;        // 0..7
    const int bcol = (tid & 31) * 4;  // 0..124

    const float* Ag = A + (size_t)(m0 + arow) * K + acol;
    const float* Bg = g_col + (size_t)brow * N + n0 + bcol;  // OOB cols read into pad (zeros)

    // preload tile 0
    float4 ar = *(const float4*)Ag;
    float4 br = *(const float4*)Bg;
    As[0][acol + 0][arow] = ar.x;
    As[0][acol + 1][arow] = ar.y;
    As[0][acol + 2][arow] = ar.z;
    As[0][acol + 3][arow] = ar.w;
    *(float4*)&Bs[0][brow][bcol] = br;
    __syncthreads();

    float acc[8][8];
#pragma unroll
    for (int i = 0; i < 8; i++)
#pragma unroll
        for (int j = 0; j < 8; j++) acc[i][j] = 0.f;

    const int nt = K / 8;   // 576
    int buf = 0;
    for (int kt = 0; kt < nt; kt++) {
        float4 an, bn;
        const bool more = (kt + 1 < nt);
        if (more) {
            an = *(const float4*)(Ag + (size_t)(kt + 1) * 8);
            bn = *(const float4*)(Bg + (size_t)(kt + 1) * 8 * N);
        }
        float af[8], bf[8];
#pragma unroll
        for (int kk = 0; kk < 8; kk++) {
            *(float4*)(af + 0) = *(float4*)&As[buf][kk][ty * 8 + 0];
            *(float4*)(af + 4) = *(float4*)&As[buf][kk][ty * 8 + 4];
            *(float4*)(bf + 0) = *(float4*)&Bs[buf][kk][tx * 8 + 0];
            *(float4*)(bf + 4) = *(float4*)&Bs[buf][kk][tx * 8 + 4];
#pragma unroll
            for (int i = 0; i < 8; i++)
#pragma unroll
                for (int j = 0; j < 8; j++)
                    acc[i][j] = fmaf(af[i], bf[j], acc[i][j]);
        }
        if (more) {
            int nb = buf ^ 1;
            As[nb][acol + 0][arow] = an.x;
            As[nb][acol + 1][arow] = an.y;
            As[nb][acol + 2][arow] = an.z;
            As[nb][acol + 3][arow] = an.w;
            *(float4*)&Bs[nb][brow][bcol] = bn;
            buf = nb;
        }
        __syncthreads();
    }

#pragma unroll
    for (int i = 0; i < 8; i++) {
        int m = m0 + ty * 8 + i;
        float bs = bias[m];
#pragma unroll
        for (int j = 0; j < 8; j++) {
            int n = n0 + tx * 8 + j;
            if (n < N)
                g_feat[(size_t)m * N + n] = fmaxf(acc[i][j] + bs, 0.f);
        }
    }
}

// ---------------- 1x1 heads: 36 loc + 18 score channels, softmax fg ----------------
__global__ __launch_bounds__(128) void head_k(
    const float* __restrict__ lw, const float* __restrict__ lb,
    const float* __restrict__ sw, const float* __restrict__ sb,
    float* __restrict__ out)
{
    __shared__ float wl[32 * 36];
    __shared__ float ws[32 * 18];
    const int n  = blockIdx.x * 128 + threadIdx.x;
    const bool act = (n < NPIX);

    float accL[36], accS[18];
#pragma unroll
    for (int j = 0; j < 36; j++) accL[j] = lb[j];
#pragma unroll
    for (int j = 0; j < 18; j++) accS[j] = sb[j];

    for (int c0 = 0; c0 < CIN; c0 += 32) {
        __syncthreads();
        for (int t = threadIdx.x; t < 32 * 36; t += 128) {
            int cc = t / 36, j = t - cc * 36;
            wl[t] = lw[(size_t)j * CIN + c0 + cc];
        }
        for (int t = threadIdx.x; t < 32 * 18; t += 128) {
            int cc = t / 18, j = t - cc * 18;
            ws[t] = sw[(size_t)j * CIN + c0 + cc];
        }
        __syncthreads();
        if (act) {
            for (int cc = 0; cc < 32; cc++) {
                float f = g_feat[(size_t)(c0 + cc) * NPIX + n];
#pragma unroll
                for (int j = 0; j < 36; j++) accL[j] = fmaf(f, wl[cc * 36 + j], accL[j]);
#pragma unroll
                for (int j = 0; j < 18; j++) accS[j] = fmaf(f, ws[cc * 18 + j], accS[j]);
            }
        }
    }

    if (act) {
        float* ol = out + OUT_LOC + (size_t)n * 36;
#pragma unroll
        for (int j = 0; j < 36; j++) ol[j] = accL[j];
        float* os = out + OUT_SCR + (size_t)n * 18;
#pragma unroll
        for (int j = 0; j < 18; j++) os[j] = accS[j];
#pragma unroll
        for (int a = 0; a < 9; a++) {
            float l0 = accS[2 * a], l1 = accS[2 * a + 1];
            float m  = fmaxf(l0, l1);
            float e0 = expf(l0 - m), e1 = expf(l1 - m);
            g_fg[(size_t)n * 9 + a] = e1 / (e0 + e1);
        }
    }
}

// ---------------- anchors ----------------
__global__ void anchor_k(float* __restrict__ out)
{
    int i = blockIdx.x * 256 + threadIdx.x;   // 0..34199  (p*9 + a)
    if (i >= ANCH) return;
    int a = i % 9, p = i / 9;
    int y = p / WW, xq = p - y * WW;
    const double ratios[3] = {0.5, 1.0, 2.0};
    const double scales[3] = {8.0, 16.0, 32.0};
    double r = ratios[a / 3], s = scales[a % 3];
    double h = 16.0 * s * sqrt(r);
    double w = 16.0 * s * sqrt(1.0 / r);
    float bx0 = (float)(8.0 - w * 0.5), by0 = (float)(8.0 - h * 0.5);
    float bx1 = (float)(8.0 + w * 0.5), by1 = (float)(8.0 + h * 0.5);
    float sx = (float)xq * 16.f, sy = (float)y * 16.f;
    float4 av = make_float4(sx + bx0, sy + by0, sx + bx1, sy + by1);
    g_anchor4[i] = av;
    float* o = out + OUT_ANC + (size_t)i * 4;
    o[0] = av.x; o[1] = av.y; o[2] = av.z; o[3] = av.w;
}

// ---------------- proposals: loc2bbox + clip + minsize + sort keys ----------------
__device__ __forceinline__ float read_dim(const int* p)
{
    int vi = *p;
    if (vi > 0 && vi < 100000) return (float)vi;      // int32 payload
    return __int_as_float(vi);                        // fp32 payload fallback
}

__global__ void boxes_k(const float* __restrict__ out,
                        const int* __restrict__ ph, const int* __restrict__ pw)
{
    int t = blockIdx.x * 256 + threadIdx.x;
    if (t >= BATCH * SORTN) return;
    int b = t >> 16;
    int i = t & (SORTN - 1);
    if (i >= ANCH) { g_keys[t] = ~0ULL; return; }

    float4 an = g_anchor4[i];
    const float* lp = out + OUT_LOC + ((size_t)b * ANCH + i) * 4;
    float l0 = lp[0], l1 = lp[1], l2 = lp[2], l3 = lp[3];

    float aw = an.z - an.x, ah = an.w - an.y;
    float ax = an.x + 0.5f * aw, ay = an.y + 0.5f * ah;
    float cx = l0 * aw + ax;
    float cy = l1 * ah + ay;
    float w  = expf(l2) * aw;
    float h  = expf(l3) * ah;
    float imw = read_dim(pw), imh = read_dim(ph);
    float x0 = fminf(fmaxf(cx - 0.5f * w, 0.f), imw);
    float y0 = fminf(fmaxf(cy - 0.5f * h, 0.f), imh);
    float x1 = fminf(fmaxf(cx + 0.5f * w, 0.f), imw);
    float y1 = fminf(fmaxf(cy + 0.5f * h, 0.f), imh);

    bool valid = ((x1 - x0) >= 16.f) && ((y1 - y0) >= 16.f);
    float sc = valid ? g_fg[(size_t)b * ANCH + i] : __int_as_float(0xff800000);

    g_boxes[(size_t)b * ANCH + i] = make_float4(x0, y0, x1, y1);

    // key: score descending, index ascending (matches lax.top_k stability)
    unsigned sbits = __float_as_uint(sc);
    unsigned ord   = (sbits & 0x80000000u) ? ~sbits : (sbits | 0x80000000u); // ascending order
    unsigned hi    = ~ord;                                                   // descending
    g_keys[t] = ((unsigned long long)hi << 32) | (unsigned)i;
}

// ---------------- per-batch bitonic sort (one block/batch, keys in gmem) ----------------
__global__ __launch_bounds__(1024) void bitonic_k()
{
    unsigned long long* k = g_keys + (size_t)blockIdx.x * SORTN;
    for (int len = 2; len <= SORTN; len <<= 1) {
        for (int s = len >> 1; s > 0; s >>= 1) {
            for (int t = threadIdx.x; t < SORTN / 2; t += 1024) {
                int i = 2 * t - (t & (s - 1));
                int j = i + s;
                bool asc = ((i & len) == 0);
                unsigned long long a = k[i], b = k[j];
                if ((a > b) == asc) { k[i] = b; k[j] = a; }
            }
            __syncthreads();
        }
    }
}

// ---------------- per-batch NMS + top-300 compact ----------------
__global__ __launch_bounds__(1024) void nms_k(float* __restrict__ out)
{
    extern __shared__ unsigned char smraw[];
    float4*        sb  = (float4*)smraw;                          // 96000 B
    float*         sar = (float*)(smraw + PRE_NMS * 16);          // 24000 B
    unsigned char* skp = (unsigned char*)(smraw + PRE_NMS * 20);  //  6000 B

    const int b   = blockIdx.x;
    const int tid = threadIdx.x;

    for (int j = tid; j < PRE_NMS; j += 1024) {
        unsigned long long key = g_keys[(size_t)b * SORTN + j];
        unsigned idx = (unsigned)(key & 0xffffffffULL);
        unsigned hi  = (unsigned)(key >> 32);
        float4 bx = g_boxes[(size_t)b * ANCH + idx];
        sb[j]  = bx;
        sar[j] = (bx.z - bx.x) * (bx.w - bx.y);
        skp[j] = (hi >> 31) ? 0 : 1;      // finite (positive) score -> keep
    }
    __syncthreads();

    for (int i = 0; i < PRE_NMS; i++) {
        if (!skp[i]) { __syncthreads(); continue; }
        float4 bi = sb[i];
        float  ai = sar[i];
        for (int j = i + 1 + tid; j < PRE_NMS; j += 1024) {
            if (!skp[j]) continue;
            float4 bj = sb[j];
            float xx1 = fmaxf(bi.x, bj.x);
            float yy1 = fmaxf(bi.y, bj.y);
            float xx2 = fminf(bi.z, bj.z);
            float yy2 = fminf(bi.w, bj.w);
            float iw = fmaxf(xx2 - xx1, 0.f);
            float ih = fmaxf(yy2 - yy1, 0.f);
            float inter = iw * ih;
            float iou = inter / (ai + sar[j] - inter + 1e-9f);
            if (iou > NMS_TH) skp[j] = 0;
        }
        __syncthreads();
    }

    // zero-fill rois region for this batch, then compact first 300 kept (score order)
    float* outroi = out + OUT_ROI + (size_t)b * POST_NMS * 4;
    for (int r = tid; r < POST_NMS * 4; r += 1024) outroi[r] = 0.f;
    __syncthreads();

    if (tid < 32) {
        int base = 0;
        for (int c0 = 0; c0 < PRE_NMS && base < POST_NMS; c0 += 32) {
            int j = c0 + tid;
            int k = (j < PRE_NMS) ? (int)skp[j] : 0;
            unsigned m = __ballot_sync(0xffffffffu, k != 0);
            if (k) {
                int r = base + __popc(m & ((1u << tid) - 1));
                if (r < POST_NMS) {
                    float4 bx = sb[j];
                    float* o = outroi + (size_t)r * 4;
                    o[0] = bx.x; o[1] = bx.y; o[2] = bx.z; o[3] = bx.w;
                }
            }
            base += __popc(m);
        }
    }
}

// ---------------- launch ----------------
extern "C" void kernel_launch(void* const* d_in, const int* in_sizes, int n_in,
                              void* d_out, int out_size)
{
    const float* x    = (const float*)d_in[0];
    const float* c1w  = (const float*)d_in[1];
    const float* c1b  = (const float*)d_in[2];
    const float* sw   = (const float*)d_in[3];
    const float* sb   = (const float*)d_in[4];
    const float* lw   = (const float*)d_in[5];
    const float* lb   = (const float*)d_in[6];
    const int*   ih   = (const int*)d_in[7];
    const int*   iw   = (const int*)d_in[8];
    float* out = (float*)d_out;

    static int smem_set = 0;
    (void)smem_set; // attribute set every call (deterministic, not a stream op)
    cudaFuncSetAttribute(nms_k, cudaFuncAttributeMaxDynamicSharedMemorySize, PRE_NMS * 21);

    im2col_k<<<dim3((NPIX + 127) / 128, KDIM), 128>>>(x);
    sgemm_bias_relu_k<<<dim3((NPIX + 127) / 128, OC / 128), 256>>>(c1w, c1b);
    head_k<<<(NPIX + 127) / 128, 128>>>(lw, lb, sw, sb, out);
    anchor_k<<<(ANCH + 255) / 256, 256>>>(out);
    boxes_k<<<(BATCH * SORTN) / 256, 256>>>(out, ih, iw);
    bitonic_k<<<BATCH, 1024>>>();
    nms_k<<<BATCH, 1024, PRE_NMS * 21>>>(out);
}

// round 4
// speedup vs baseline: 1.9390x; 1.9390x over previous
#include <cuda_runtime.h>
#include <math.h>
#include <stdint.h>

// ---------------- problem constants ----------------
#define BATCH   8
#define CIN     512
#define HH      50
#define WW      76
#define HW      3800
#define NPIX    30400
#define KDIM    4608
#define OC      512
#define ANCH    34200
#define SORTN   65536
#define PRE_NMS 6000
#define POST_NMS 300
#define NMS_TH  0.7f
#define NW      96              // 64-bit mask words per NMS row (94 used)

#define OUT_LOC 0
#define OUT_SCR 1094400
#define OUT_ROI 1641600
#define OUT_ANC 1651200

// ---------------- device scratch ----------------
__device__ float              g_col [(size_t)KDIM * NPIX + 128];
__device__ float              g_feat[(size_t)OC * NPIX];
__device__ float              g_fg  [BATCH * ANCH];
__device__ float4             g_boxes[BATCH * ANCH];
__device__ float4             g_anchor4[ANCH];
__device__ unsigned long long g_keys[BATCH * SORTN];
__device__ float4             g_sbox[BATCH][PRE_NMS];
__device__ float              g_sarea[BATCH][PRE_NMS];
__device__ unsigned long long g_rminit[BATCH][NW];
__device__ unsigned long long g_mask[BATCH][PRE_NMS][NW];   // ~37 MB

// ---------------- im2col ----------------
__global__ void im2col_k(const float* __restrict__ x)
{
    int n = blockIdx.x * 128 + threadIdx.x;
    int k = blockIdx.y;
    if (n >= NPIX) return;
    int c  = k / 9;
    int r  = k - c * 9;
    int ky = r / 3, kx = r - (r / 3) * 3;
    int b  = n / HW;
    int p  = n - b * HW;
    int y  = p / WW;
    int xq = p - y * WW;
    int yy = y + ky - 1, xx = xq + kx - 1;
    float v = 0.f;
    if (yy >= 0 && yy < HH && xx >= 0 && xx < WW)
        v = x[(((size_t)b * CIN + c) * HH + yy) * WW + xx];
    g_col[(size_t)k * NPIX + n] = v;
}

// ---------------- FFMA2 helpers ----------------
__device__ __forceinline__ void ffma2(unsigned long long& d, unsigned long long a, unsigned long long b)
{
    asm("fma.rn.f32x2 %0, %1, %2, %0;" : "+l"(d) : "l"(a), "l"(b));
}
__device__ __forceinline__ unsigned long long dup2(float x)
{
    unsigned long long r; asm("mov.b64 %0, {%1, %1};" : "=l"(r) : "f"(x)); return r;
}
__device__ __forceinline__ float2 unpk(unsigned long long v)
{
    float2 r; asm("mov.b64 {%0, %1}, %2;" : "=f"(r.x), "=f"(r.y) : "l"(v)); return r;
}

// ---------------- SGEMM 512 x 30400 x 4608 (fp32 via f32x2), bias + relu ----------------
// BM=256, BN=128, BK=8, 256 threads, 16x8 per thread (row pairs packed in f32x2)
__global__ __launch_bounds__(256, 1) void sgemm_bias_relu_k(
    const float* __restrict__ A, const float* __restrict__ bias)
{
    const int N = NPIX, K = KDIM;
    __shared__ float As[2][8][256];
    __shared__ float Bs[2][8][128];

    const int tid = threadIdx.x;
    const int m0  = blockIdx.y * 256;
    const int n0  = blockIdx.x * 128;
    const int tx  = tid & 15;
    const int ty  = tid >> 4;

    const float* Ag = A + (size_t)(m0 + tid) * K;
    const float* Bg = g_col + (size_t)(tid >> 5) * N + n0 + (tid & 31) * 4;

    {   // preload tile 0
        float4 a0 = *(const float4*)Ag;
        float4 a1 = *(const float4*)(Ag + 4);
        float4 b0 = *(const float4*)Bg;
        As[0][0][tid] = a0.x; As[0][1][tid] = a0.y; As[0][2][tid] = a0.z; As[0][3][tid] = a0.w;
        As[0][4][tid] = a1.x; As[0][5][tid] = a1.y; As[0][6][tid] = a1.z; As[0][7][tid] = a1.w;
        *(float4*)&Bs[0][tid >> 5][(tid & 31) * 4] = b0;
    }
    __syncthreads();

    unsigned long long acc[8][8];
#pragma unroll
    for (int i = 0; i < 8; i++)
#pragma unroll
        for (int j = 0; j < 8; j++) acc[i][j] = 0ULL;

    const int nt = K / 8;   // 576
    int buf = 0;
    for (int kt = 0; kt < nt; kt++) {
        float4 an0, an1, bn;
        const bool more = (kt + 1 < nt);
        if (more) {
            an0 = *(const float4*)(Ag + (size_t)(kt + 1) * 8);
            an1 = *(const float4*)(Ag + (size_t)(kt + 1) * 8 + 4);
            bn  = *(const float4*)(Bg + (size_t)(kt + 1) * 8 * N);
        }
#pragma unroll
        for (int kk = 0; kk < 8; kk++) {
            const float* ap = &As[buf][kk][ty * 16];
            ulonglong2 t0 = *(const ulonglong2*)(ap + 0);
            ulonglong2 t1 = *(const ulonglong2*)(ap + 4);
            ulonglong2 t2 = *(const ulonglong2*)(ap + 8);
            ulonglong2 t3 = *(const ulonglong2*)(ap + 12);
            unsigned long long a2[8];
            a2[0] = t0.x; a2[1] = t0.y; a2[2] = t1.x; a2[3] = t1.y;
            a2[4] = t2.x; a2[5] = t2.y; a2[6] = t3.x; a2[7] = t3.y;
            float4 bx = *(const float4*)&Bs[buf][kk][tx * 8];
            float4 by = *(const float4*)&Bs[buf][kk][tx * 8 + 4];
            unsigned long long bd[8];
            bd[0] = dup2(bx.x); bd[1] = dup2(bx.y); bd[2] = dup2(bx.z); bd[3] = dup2(bx.w);
            bd[4] = dup2(by.x); bd[5] = dup2(by.y); bd[6] = dup2(by.z); bd[7] = dup2(by.w);
#pragma unroll
            for (int i = 0; i < 8; i++)
#pragma unroll
                for (int j = 0; j < 8; j++)
                    ffma2(acc[i][j], a2[i], bd[j]);
        }
        if (more) {
            int nb = buf ^ 1;
            As[nb][0][tid] = an0.x; As[nb][1][tid] = an0.y; As[nb][2][tid] = an0.z; As[nb][3][tid] = an0.w;
            As[nb][4][tid] = an1.x; As[nb][5][tid] = an1.y; As[nb][6][tid] = an1.z; As[nb][7][tid] = an1.w;
            *(float4*)&Bs[nb][tid >> 5][(tid & 31) * 4] = bn;
            buf = nb;
        }
        __syncthreads();
    }

    // epilogue: each acc[i][j] holds rows (2i, 2i+1) of this thread's 16-row strip, col j
#pragma unroll
    for (int i = 0; i < 8; i++) {
        int me = m0 + ty * 16 + i * 2;
        float be = bias[me], bo = bias[me + 1];
        float re[8], ro[8];
#pragma unroll
        for (int j = 0; j < 8; j++) {
            float2 v = unpk(acc[i][j]);
            re[j] = fmaxf(v.x + be, 0.f);
            ro[j] = fmaxf(v.y + bo, 0.f);
        }
        int n = n0 + tx * 8;
        if (n + 7 < N) {
            *(float4*)&g_feat[(size_t)me * N + n]       = make_float4(re[0], re[1], re[2], re[3]);
            *(float4*)&g_feat[(size_t)me * N + n + 4]   = make_float4(re[4], re[5], re[6], re[7]);
            *(float4*)&g_feat[(size_t)(me + 1) * N + n]     = make_float4(ro[0], ro[1], ro[2], ro[3]);
            *(float4*)&g_feat[(size_t)(me + 1) * N + n + 4] = make_float4(ro[4], ro[5], ro[6], ro[7]);
        } else {
#pragma unroll
            for (int j = 0; j < 8; j++) if (n + j < N) {
                g_feat[(size_t)me * N + n + j]       = re[j];
                g_feat[(size_t)(me + 1) * N + n + j] = ro[j];
            }
        }
    }
}

// ---------------- 1x1 heads ----------------
__global__ __launch_bounds__(128) void head_k(
    const float* __restrict__ lw, const float* __restrict__ lb,
    const float* __restrict__ sw, const float* __restrict__ sb,
    float* __restrict__ out)
{
    __shared__ float wl[32 * 36];
    __shared__ float ws[32 * 18];
    const int n  = blockIdx.x * 128 + threadIdx.x;
    const bool act = (n < NPIX);

    float accL[36], accS[18];
#pragma unroll
    for (int j = 0; j < 36; j++) accL[j] = lb[j];
#pragma unroll
    for (int j = 0; j < 18; j++) accS[j] = sb[j];

    for (int c0 = 0; c0 < CIN; c0 += 32) {
        __syncthreads();
        for (int t = threadIdx.x; t < 32 * 36; t += 128) {
            int cc = t / 36, j = t - cc * 36;
            wl[t] = lw[(size_t)j * CIN + c0 + cc];
        }
        for (int t = threadIdx.x; t < 32 * 18; t += 128) {
            int cc = t / 18, j = t - cc * 18;
            ws[t] = sw[(size_t)j * CIN + c0 + cc];
        }
        __syncthreads();
        if (act) {
            for (int cc = 0; cc < 32; cc++) {
                float f = g_feat[(size_t)(c0 + cc) * NPIX + n];
#pragma unroll
                for (int j = 0; j < 36; j++) accL[j] = fmaf(f, wl[cc * 36 + j], accL[j]);
#pragma unroll
                for (int j = 0; j < 18; j++) accS[j] = fmaf(f, ws[cc * 18 + j], accS[j]);
            }
        }
    }

    if (act) {
        float* ol = out + OUT_LOC + (size_t)n * 36;
#pragma unroll
        for (int j = 0; j < 36; j++) ol[j] = accL[j];
        float* os = out + OUT_SCR + (size_t)n * 18;
#pragma unroll
        for (int j = 0; j < 18; j++) os[j] = accS[j];
#pragma unroll
        for (int a = 0; a < 9; a++) {
            float l0 = accS[2 * a], l1 = accS[2 * a + 1];
            float m  = fmaxf(l0, l1);
            float e0 = expf(l0 - m), e1 = expf(l1 - m);
            g_fg[(size_t)n * 9 + a] = e1 / (e0 + e1);
        }
    }
}

// ---------------- anchors ----------------
__global__ void anchor_k(float* __restrict__ out)
{
    int i = blockIdx.x * 256 + threadIdx.x;
    if (i >= ANCH) return;
    int a = i % 9, p = i / 9;
    int y = p / WW, xq = p - y * WW;
    const double ratios[3] = {0.5, 1.0, 2.0};
    const double scales[3] = {8.0, 16.0, 32.0};
    double r = ratios[a / 3], s = scales[a % 3];
    double h = 16.0 * s * sqrt(r);
    double w = 16.0 * s * sqrt(1.0 / r);
    float bx0 = (float)(8.0 - w * 0.5), by0 = (float)(8.0 - h * 0.5);
    float bx1 = (float)(8.0 + w * 0.5), by1 = (float)(8.0 + h * 0.5);
    float sx = (float)xq * 16.f, sy = (float)y * 16.f;
    float4 av = make_float4(sx + bx0, sy + by0, sx + bx1, sy + by1);
    g_anchor4[i] = av;
    float* o = out + OUT_ANC + (size_t)i * 4;
    o[0] = av.x; o[1] = av.y; o[2] = av.z; o[3] = av.w;
}

// ---------------- proposals + sort keys ----------------
__device__ __forceinline__ float read_dim(const int* p)
{
    int vi = *p;
    if (vi > 0 && vi < 100000) return (float)vi;
    return __int_as_float(vi);
}

__global__ void boxes_k(const float* __restrict__ out,
                        const int* __restrict__ ph, const int* __restrict__ pw)
{
    int t = blockIdx.x * 256 + threadIdx.x;
    if (t < BATCH * NW) ((unsigned long long*)g_rminit)[t] = 0ULL;
    if (t >= BATCH * SORTN) return;
    int b = t >> 16;
    int i = t & (SORTN - 1);
    if (i >= ANCH) { g_keys[t] = ~0ULL; return; }

    float4 an = g_anchor4[i];
    const float* lp = out + OUT_LOC + ((size_t)b * ANCH + i) * 4;
    float l0 = lp[0], l1 = lp[1], l2 = lp[2], l3 = lp[3];

    float aw = an.z - an.x, ah = an.w - an.y;
    float ax = an.x + 0.5f * aw, ay = an.y + 0.5f * ah;
    float cx = l0 * aw + ax;
    float cy = l1 * ah + ay;
    float w  = expf(l2) * aw;
    float h  = expf(l3) * ah;
    float imw = read_dim(pw), imh = read_dim(ph);
    float x0 = fminf(fmaxf(cx - 0.5f * w, 0.f), imw);
    float y0 = fminf(fmaxf(cy - 0.5f * h, 0.f), imh);
    float x1 = fminf(fmaxf(cx + 0.5f * w, 0.f), imw);
    float y1 = fminf(fmaxf(cy + 0.5f * h, 0.f), imh);

    bool valid = ((x1 - x0) >= 16.f) && ((y1 - y0) >= 16.f);
    float sc = valid ? g_fg[(size_t)b * ANCH + i] : __int_as_float(0xff800000);

    g_boxes[(size_t)b * ANCH + i] = make_float4(x0, y0, x1, y1);

    unsigned sbits = __float_as_uint(sc);
    unsigned ord   = (sbits & 0x80000000u) ? ~sbits : (sbits | 0x80000000u);
    unsigned hi    = ~ord;
    g_keys[t] = ((unsigned long long)hi << 32) | (unsigned)i;
}

// ---------------- staged bitonic sort (exact, 64-block parallel) ----------------
__global__ void sort8k_k()
{
    extern __shared__ unsigned long long sk[];
    const int tid = threadIdx.x;
    const size_t base = (size_t)blockIdx.x * 8192;
#pragma unroll
    for (int r = 0; r < 8; r++) sk[tid + r * 1024] = g_keys[base + tid + r * 1024];
    __syncthreads();
    const unsigned gb = (unsigned)(base & (SORTN - 1));
    for (int len = 2; len <= 8192; len <<= 1) {
        for (int s = len >> 1; s > 0; s >>= 1) {
            for (int t = tid; t < 4096; t += 1024) {
                int i = 2 * t - (t & (s - 1));
                int j = i + s;
                bool asc = (((gb + i) & len) == 0);
                unsigned long long a = sk[i], b = sk[j];
                if ((a > b) == asc) { sk[i] = b; sk[j] = a; }
            }
            __syncthreads();
        }
    }
#pragma unroll
    for (int r = 0; r < 8; r++) g_keys[base + tid + r * 1024] = sk[tid + r * 1024];
}

__global__ void gpass_k(int len, int s)
{
    int t = blockIdx.x * 256 + threadIdx.x;    // 262144 pairs
    int b = t >> 15;
    int tt = t & 32767;
    int i = 2 * tt - (tt & (s - 1));
    int j = i + s;
    bool asc = ((i & len) == 0);
    unsigned long long* k = g_keys + (size_t)b * SORTN;
    unsigned long long a = k[i], c = k[j];
    if ((a > c) == asc) { k[i] = c; k[j] = a; }
}

__global__ void tail_k(int len)
{
    extern __shared__ unsigned long long sk[];
    const int tid = threadIdx.x;
    const size_t base = (size_t)blockIdx.x * 8192;
#pragma unroll
    for (int r = 0; r < 8; r++) sk[tid + r * 1024] = g_keys[base + tid + r * 1024];
    __syncthreads();
    const bool asc = (((unsigned)(base & (SORTN - 1)) & (unsigned)len) == 0);
    for (int s = 4096; s > 0; s >>= 1) {
        for (int t = tid; t < 4096; t += 1024) {
            int i = 2 * t - (t & (s - 1));
            int j = i + s;
            unsigned long long a = sk[i], b = sk[j];
            if ((a > b) == asc) { sk[i] = b; sk[j] = a; }
        }
        __syncthreads();
    }
#pragma unroll
    for (int r = 0; r < 8; r++) g_keys[base + tid + r * 1024] = sk[tid + r * 1024];
}

// ---------------- NMS: gather sorted boxes ----------------
__global__ void gather_k()
{
    int b = blockIdx.x;
    int j = blockIdx.y * 1024 + threadIdx.x;
    if (j >= PRE_NMS) return;
    unsigned long long key = g_keys[(size_t)b * SORTN + j];
    unsigned idx = (unsigned)key;
    unsigned hi  = (unsigned)(key >> 32);
    float4 bx = g_boxes[(size_t)b * ANCH + idx];
    g_sbox[b][j]  = bx;
    g_sarea[b][j] = (bx.z - bx.x) * (bx.w - bx.y);
    if (hi >> 31) atomicOr(&g_rminit[b][j >> 6], 1ULL << (j & 63));
}

// ---------------- NMS: suppression mask matrix ----------------
__global__ __launch_bounds__(256) void mask_k()
{
    __shared__ float4 sjb[512];
    __shared__ float  sja[512];
    int b     = blockIdx.z;
    int jbase = blockIdx.x * 512;
    int i     = blockIdx.y * 32 + (threadIdx.x & 31);
    int w     = (jbase >> 6) + (threadIdx.x >> 5);

    for (int t = threadIdx.x; t < 512; t += 256) {
        int j = jbase + t;
        if (j < PRE_NMS) { sjb[t] = g_sbox[b][j]; sja[t] = g_sarea[b][j]; }
        else             { sjb[t] = make_float4(0, 0, 0, 0); sja[t] = 0.f; }
    }
    __syncthreads();
    if (i >= PRE_NMS) return;

    float4 bi = g_sbox[b][i];
    float  ai = g_sarea[b][i];
    unsigned long long bits = 0;
    if (w * 64 + 63 > i) {
        int tj0 = w * 64 - jbase;
#pragma unroll 8
        for (int bit = 0; bit < 64; bit++) {
            int j = w * 64 + bit;
            if (j > i && j < PRE_NMS) {
                float4 bj = sjb[tj0 + bit];
                float xx1 = fmaxf(bi.x, bj.x);
                float yy1 = fmaxf(bi.y, bj.y);
                float xx2 = fminf(bi.z, bj.z);
                float yy2 = fminf(bi.w, bj.w);
                float iw = fmaxf(xx2 - xx1, 0.f);
                float ih = fmaxf(yy2 - yy1, 0.f);
                float inter = iw * ih;
                float iou = inter / (ai + sja[tj0 + bit] - inter + 1e-9f);
                if (iou > NMS_TH) bits |= 1ULL << bit;
            }
        }
    }
    g_mask[b][i][w] = bits;
}

// ---------------- NMS: warp-sequential reduce with early exit ----------------
__global__ void reduce_k(float* __restrict__ out)
{
    int b = blockIdx.x, lane = threadIdx.x;
    unsigned long long rm0 = g_rminit[b][lane];
    unsigned long long rm1 = g_rminit[b][lane + 32];
    unsigned long long rm2 = g_rminit[b][lane + 64];

    float* outroi = out + OUT_ROI + (size_t)b * POST_NMS * 4;
    for (int r = lane; r < POST_NMS * 4; r += 32) outroi[r] = 0.f;
    __syncwarp();

    int kc = 0;
    for (int i = 0; i < PRE_NMS; i++) {
        int w = i >> 6, slot = w >> 5, owner = w & 31;
        unsigned long long mine = (slot == 0) ? rm0 : ((slot == 1) ? rm1 : rm2);
        unsigned long long wv = __shfl_sync(0xffffffffu, mine, owner);
        if (!((wv >> (i & 63)) & 1ULL)) {
            if (lane < 4)
                outroi[kc * 4 + lane] = ((const float*)&g_sbox[b][i])[lane];
            kc++;
            if (kc == POST_NMS) break;
            const unsigned long long* mrow = g_mask[b][i];
            rm0 |= mrow[lane];
            rm1 |= mrow[lane + 32];
            rm2 |= mrow[lane + 64];
        }
    }
}

// ---------------- launch ----------------
extern "C" void kernel_launch(void* const* d_in, const int* in_sizes, int n_in,
                              void* d_out, int out_size)
{
    const float* x   = (const float*)d_in[0];
    const float* c1w = (const float*)d_in[1];
    const float* c1b = (const float*)d_in[2];
    const float* sw  = (const float*)d_in[3];
    const float* sb  = (const float*)d_in[4];
    const float* lw  = (const float*)d_in[5];
    const float* lb  = (const float*)d_in[6];
    const int*   ih  = (const int*)d_in[7];
    const int*   iw  = (const int*)d_in[8];
    float* out = (float*)d_out;

    cudaFuncSetAttribute(sort8k_k, cudaFuncAttributeMaxDynamicSharedMemorySize, 65536);
    cudaFuncSetAttribute(tail_k,   cudaFuncAttributeMaxDynamicSharedMemorySize, 65536);

    im2col_k<<<dim3((NPIX + 127) / 128, KDIM), 128>>>(x);
    sgemm_bias_relu_k<<<dim3((NPIX + 127) / 128, OC / 256), 256>>>(c1w, c1b);
    head_k<<<(NPIX + 127) / 128, 128>>>(lw, lb, sw, sb, out);
    anchor_k<<<(ANCH + 255) / 256, 256>>>(out);
    boxes_k<<<(BATCH * SORTN) / 256, 256>>>(out, ih, iw);

    sort8k_k<<<64, 1024, 65536>>>();
    gpass_k<<<1024, 256>>>(16384, 8192);
    tail_k<<<64, 1024, 65536>>>(16384);
    gpass_k<<<1024, 256>>>(32768, 16384);
    gpass_k<<<1024, 256>>>(32768, 8192);
    tail_k<<<64, 1024, 65536>>>(32768);
    gpass_k<<<1024, 256>>>(65536, 32768);
    gpass_k<<<1024, 256>>>(65536, 16384);
    gpass_k<<<1024, 256>>>(65536, 8192);
    tail_k<<<64, 1024, 65536>>>(65536);

    gather_k<<<dim3(8, 6), 1024>>>();
    mask_k<<<dim3(12, 188, 8), 256>>>();
    reduce_k<<<8, 32>>>(out);
}

// round 10
// speedup vs baseline: 2.0824x; 1.0740x over previous
#include <cuda_runtime.h>
#include <cuda_bf16.h>
#include <math.h>
#include <stdint.h>

// ---------------- problem constants ----------------
#define BATCH   8
#define CIN     512
#define HH      50
#define WW      76
#define HW      3800
#define NPIX    30400
#define KDIM    4608
#define OC      512
#define ANCH    34200
#define SORTN   65536
#define PRE_NMS 6000
#define POST_NMS 300
#define NMS_TH  0.7f
#define NW      96

#define OUT_LOC 0
#define OUT_SCR 1094400
#define OUT_ROI 1641600
#define OUT_ANC 1651200

#define ZROW    30400
#define BTROWS  30401
#define KC      64
#define NCHUNK  72              // 9 offsets * 8 c-chunks of 64
#define STG     98304           // per-stage smem: 3 A planes + 3 B planes, 16KB each

// ---------------- device scratch ----------------
__device__ __align__(16) float         g_feat[(size_t)OC * NPIX];
__device__ __align__(16) __nv_bfloat16 g_Awt[3][9][OC][CIN];        // 14 MB
__device__ __align__(16) __nv_bfloat16 g_Bt [3][BTROWS][CIN];       // 93 MB (row ZROW stays zero)
__device__ float              g_fg  [BATCH * ANCH];
__device__ float4             g_boxes[BATCH * ANCH];
__device__ float4             g_anchor4[ANCH];
__device__ unsigned long long g_keys[BATCH * SORTN];
__device__ float4             g_sbox[BATCH][PRE_NMS];
__device__ float              g_sarea[BATCH][PRE_NMS];
__device__ unsigned long long g_rminit[BATCH][NW];
__device__ unsigned long long g_mask[BATCH][PRE_NMS][NW];

// ---------------- fp32 -> 3x bf16 exact split ----------------
__device__ __forceinline__ void split3(float v, __nv_bfloat16& b0, __nv_bfloat16& b1, __nv_bfloat16& b2)
{
    b0 = __float2bfloat16(v);
    float r1 = v - __bfloat162float(b0);
    b1 = __float2bfloat16(r1);
    float r2 = r1 - __bfloat162float(b1);
    b2 = __float2bfloat16(r2);
}

// ---------------- A split: w[oc][c][3][3] -> g_Awt[p][off][oc][c] ----------------
__global__ void asplit_k(const float* __restrict__ w)
{
    int i = blockIdx.x * 256 + threadIdx.x;      // oc*512 + c
    if (i >= OC * CIN) return;
    int oc = i >> 9, c = i & 511;
    const float* src = w + (size_t)oc * KDIM + c * 9;
#pragma unroll
    for (int off = 0; off < 9; off++) {
        __nv_bfloat16 p0, p1, p2;
        split3(src[off], p0, p1, p2);
        g_Awt[0][off][oc][c] = p0;
        g_Awt[1][off][oc][c] = p1;
        g_Awt[2][off][oc][c] = p2;
    }
}

// ---------------- B transpose+split: x[b][c][pix] -> g_Bt[p][n][c] ----------------
__global__ __launch_bounds__(256) void tsplit_k(const float* __restrict__ x)
{
    __shared__ float s[32][33];
    int pt = blockIdx.x, ct = blockIdx.y, b = blockIdx.z;
    int tx = threadIdx.x & 31, ty = threadIdx.x >> 5;   // (32,8)
#pragma unroll
    for (int i = 0; i < 4; i++) {
        int cl = ty + i * 8;
        int pix = pt * 32 + tx;
        float v = 0.f;
        if (pix < HW)
            v = x[((size_t)b * CIN + ct * 32 + cl) * HW + pix];
        s[cl][tx] = v;
    }
    __syncthreads();
#pragma unroll
    for (int i = 0; i < 4; i++) {
        int pl = ty + i * 8;
        int pix = pt * 32 + pl;
        if (pix < HW) {
            int n = b * HW + pix;
            int c = ct * 32 + tx;
            __nv_bfloat16 p0, p1, p2;
            split3(s[tx][pl], p0, p1, p2);
            g_Bt[0][n][c] = p0;
            g_Bt[1][n][c] = p1;
            g_Bt[2][n][c] = p2;
        }
    }
}

// ---------------- helpers ----------------
__device__ __forceinline__ uint32_t smem_u32(const void* p)
{
    uint32_t a;
    asm("{ .reg .u64 t; cvta.to.shared.u64 t, %1; cvt.u32.u64 %0, t; }" : "=r"(a) : "l"(p));
    return a;
}
__device__ __forceinline__ void cp16(uint32_t dst, const void* src)
{
    asm volatile("cp.async.cg.shared.global [%0], [%1], 16;" :: "r"(dst), "l"(src));
}
__device__ __forceinline__ void ldm4(uint32_t* r, uint32_t addr)
{
    asm volatile("ldmatrix.sync.aligned.m8n8.x4.shared.b16 {%0,%1,%2,%3}, [%4];"
                 : "=r"(r[0]), "=r"(r[1]), "=r"(r[2]), "=r"(r[3]) : "r"(addr));
}
__device__ __forceinline__ void hmma(float* d, const uint32_t* a, uint32_t b0, uint32_t b1)
{
    asm volatile(
        "mma.sync.aligned.m16n8k16.row.col.f32.bf16.bf16.f32 "
        "{%0,%1,%2,%3}, {%4,%5,%6,%7}, {%8,%9}, {%0,%1,%2,%3};"
        : "+f"(d[0]), "+f"(d[1]), "+f"(d[2]), "+f"(d[3])
        : "r"(a[0]), "r"(a[1]), "r"(a[2]), "r"(a[3]), "r"(b0), "r"(b1));
}

// ---------------- HMMA GEMM: feat = relu(W*col + bias) via direct conv ----------------
// CTA 128m x 128n, KC=64; per chunk load 3 A planes + 3 B planes, issue 6 pair MMAs.
// Precision: dominant plane pair (0,0) accumulates into accM (288 steps -> ~1e-6 noise);
// the 5 correction pairs accumulate into accC (magnitude ~2^-9 of main, noise negligible).
__global__ __launch_bounds__(256, 1) void hmma_gemm_k(const float* __restrict__ bias)
{
    extern __shared__ __align__(1024) unsigned char sm[];
    const int tid  = threadIdx.x;
    const int n0   = blockIdx.x * 128, m0 = blockIdx.y * 128;
    const int wid  = tid >> 5, lane = tid & 31;
    const int wm   = wid & 1, wn = wid >> 1;           // warp: m block 64, n block 32
    const uint32_t smb = smem_u32(sm);

    // fill-role precompute: thread covers row r, k-half h
    const int r = tid >> 1, h = tid & 1;
    const int nB = n0 + r;
    const bool nvalid = nB < NPIX;
    const int pp = nvalid ? (nB % HW) : 0;
    const int yy = pp / WW, xx = pp - yy * WW;

    float accM[4][4][4];
    float accC[4][4][4];
#pragma unroll
    for (int a = 0; a < 4; a++)
#pragma unroll
        for (int b = 0; b < 4; b++)
#pragma unroll
            for (int c = 0; c < 4; c++) { accM[a][b][c] = 0.f; accC[a][b][c] = 0.f; }

    auto fill = [&](int stage, int chunk) {
        int off = chunk >> 3, cc = (chunk & 7) * KC;
        int dy = off / 3 - 1, dx = off - (off / 3) * 3 - 1;
        int ny = yy + dy, nx = xx + dx;
        size_t np = (nvalid && ny >= 0 && ny < HH && nx >= 0 && nx < WW)
                  ? (size_t)(nB + dy * WW + dx) : (size_t)ZROW;
        uint32_t sbase = smb + stage * STG;
#pragma unroll
        for (int p = 0; p < 3; p++) {
            const __nv_bfloat16* As = &g_Awt[p][off][m0 + r][cc + h * 32];
            const __nv_bfloat16* Bs = &g_Bt[p][0][0] + np * CIN + cc + h * 32;
#pragma unroll
            for (int q = 0; q < 4; q++) {
                uint32_t o = r * 128 + (h * 4 + q) * 16;
                o ^= (o >> 3) & 0x70;
                cp16(sbase + p * 16384 + o,         As + q * 8);
                cp16(sbase + 49152 + p * 16384 + o, Bs + q * 8);
            }
        }
        asm volatile("cp.async.commit_group;");
    };

    const int pa[6] = {0, 1, 2, 0, 1, 0};
    const int pb[6] = {0, 0, 0, 1, 1, 2};

    auto compute = [&](int stage) {
        uint32_t aB = smb + stage * STG;
        uint32_t bB = aB + 49152;
#pragma unroll
        for (int pr = 0; pr < 6; pr++) {
            uint32_t at = aB + pa[pr] * 16384;
            uint32_t bt = bB + pb[pr] * 16384;
#pragma unroll
            for (int k16 = 0; k16 < 4; k16++) {
                uint32_t kb = k16 * 32 + (lane >> 4) * 16;
                uint32_t af[4][4];
#pragma unroll
                for (int mf = 0; mf < 4; mf++) {
                    uint32_t o = (wm * 64 + mf * 16 + (lane & 15)) * 128 + kb;
                    o ^= (o >> 3) & 0x70;
                    ldm4(af[mf], at + o);
                }
                uint32_t bfr[2][4];
#pragma unroll
                for (int g = 0; g < 2; g++) {
                    uint32_t o = (wn * 32 + g * 16 + (lane & 15)) * 128 + kb;
                    o ^= (o >> 3) & 0x70;
                    ldm4(bfr[g], bt + o);
                }
                if (pr == 0) {
#pragma unroll
                    for (int mf = 0; mf < 4; mf++)
#pragma unroll
                        for (int nf = 0; nf < 4; nf++)
                            hmma(accM[mf][nf], af[mf], bfr[nf >> 1][nf & 1], bfr[nf >> 1][(nf & 1) + 2]);
                } else {
#pragma unroll
                    for (int mf = 0; mf < 4; mf++)
#pragma unroll
                        for (int nf = 0; nf < 4; nf++)
                            hmma(accC[mf][nf], af[mf], bfr[nf >> 1][nf & 1], bfr[nf >> 1][(nf & 1) + 2]);
                }
            }
        }
    };

    fill(0, 0);
    fill(1, 1);
    int buf = 0;
    for (int c = 0; c < NCHUNK; c++) {
        asm volatile("cp.async.wait_group 1;");
        __syncthreads();
        compute(buf);
        __syncthreads();
        if (c + 2 < NCHUNK) fill(buf, c + 2);
        buf ^= 1;
    }

    // epilogue: main + correction, bias + relu, write g_feat[m][n]
#pragma unroll
    for (int mf = 0; mf < 4; mf++) {
        int m = m0 + wm * 64 + mf * 16 + (lane >> 2);
        float bv0 = bias[m], bv1 = bias[m + 8];
#pragma unroll
        for (int nf = 0; nf < 4; nf++) {
            int n = n0 + wn * 32 + nf * 8 + (lane & 3) * 2;
            if (n < NPIX) {
                float s0 = accM[mf][nf][0] + accC[mf][nf][0];
                float s1 = accM[mf][nf][1] + accC[mf][nf][1];
                float s2 = accM[mf][nf][2] + accC[mf][nf][2];
                float s3 = accM[mf][nf][3] + accC[mf][nf][3];
                float2 v0 = make_float2(fmaxf(s0 + bv0, 0.f), fmaxf(s1 + bv0, 0.f));
                float2 v1 = make_float2(fmaxf(s2 + bv1, 0.f), fmaxf(s3 + bv1, 0.f));
                *(float2*)&g_feat[(size_t)m * NPIX + n]       = v0;
                *(float2*)&g_feat[(size_t)(m + 8) * NPIX + n] = v1;
            }
        }
    }
}

// ---------------- 1x1 heads ----------------
__global__ __launch_bounds__(128) void head_k(
    const float* __restrict__ lw, const float* __restrict__ lb,
    const float* __restrict__ sw, const float* __restrict__ sb,
    float* __restrict__ out)
{
    __shared__ float wl[32 * 36];
    __shared__ float ws[32 * 18];
    const int n  = blockIdx.x * 128 + threadIdx.x;
    const bool act = (n < NPIX);

    float accL[36], accS[18];
#pragma unroll
    for (int j = 0; j < 36; j++) accL[j] = lb[j];
#pragma unroll
    for (int j = 0; j < 18; j++) accS[j] = sb[j];

    for (int c0 = 0; c0 < CIN; c0 += 32) {
        __syncthreads();
        for (int t = threadIdx.x; t < 32 * 36; t += 128) {
            int cc = t / 36, j = t - cc * 36;
            wl[t] = lw[(size_t)j * CIN + c0 + cc];
        }
        for (int t = threadIdx.x; t < 32 * 18; t += 128) {
            int cc = t / 18, j = t - cc * 18;
            ws[t] = sw[(size_t)j * CIN + c0 + cc];
        }
        __syncthreads();
        if (act) {
            for (int cc = 0; cc < 32; cc++) {
                float f = g_feat[(size_t)(c0 + cc) * NPIX + n];
#pragma unroll
                for (int j = 0; j < 36; j++) accL[j] = fmaf(f, wl[cc * 36 + j], accL[j]);
#pragma unroll
                for (int j = 0; j < 18; j++) accS[j] = fmaf(f, ws[cc * 18 + j], accS[j]);
            }
        }
    }

    if (act) {
        float* ol = out + OUT_LOC + (size_t)n * 36;
#pragma unroll
        for (int j = 0; j < 36; j++) ol[j] = accL[j];
        float* os = out + OUT_SCR + (size_t)n * 18;
#pragma unroll
        for (int j = 0; j < 18; j++) os[j] = accS[j];
#pragma unroll
        for (int a = 0; a < 9; a++) {
            float l0 = accS[2 * a], l1 = accS[2 * a + 1];
            float m  = fmaxf(l0, l1);
            float e0 = expf(l0 - m), e1 = expf(l1 - m);
            g_fg[(size_t)n * 9 + a] = e1 / (e0 + e1);
        }
    }
}

// ---------------- anchors ----------------
__global__ void anchor_k(float* __restrict__ out)
{
    int i = blockIdx.x * 256 + threadIdx.x;
    if (i >= ANCH) return;
    int a = i % 9, p = i / 9;
    int y = p / WW, xq = p - y * WW;
    const double ratios[3] = {0.5, 1.0, 2.0};
    const double scales[3] = {8.0, 16.0, 32.0};
    double r = ratios[a / 3], s = scales[a % 3];
    double h = 16.0 * s * sqrt(r);
    double w = 16.0 * s * sqrt(1.0 / r);
    float bx0 = (float)(8.0 - w * 0.5), by0 = (float)(8.0 - h * 0.5);
    float bx1 = (float)(8.0 + w * 0.5), by1 = (float)(8.0 + h * 0.5);
    float sx = (float)xq * 16.f, sy = (float)y * 16.f;
    float4 av = make_float4(sx + bx0, sy + by0, sx + bx1, sy + by1);
    g_anchor4[i] = av;
    float* o = out + OUT_ANC + (size_t)i * 4;
    o[0] = av.x; o[1] = av.y; o[2] = av.z; o[3] = av.w;
}

// ---------------- proposals + sort keys ----------------
__device__ __forceinline__ float read_dim(const int* p)
{
    int vi = *p;
    if (vi > 0 && vi < 100000) return (float)vi;
    return __int_as_float(vi);
}

__global__ void boxes_k(const float* __restrict__ out,
                        const int* __restrict__ ph, const int* __restrict__ pw)
{
    int t = blockIdx.x * 256 + threadIdx.x;
    if (t < BATCH * NW) ((unsigned long long*)g_rminit)[t] = 0ULL;
    if (t >= BATCH * SORTN) return;
    int b = t >> 16;
    int i = t & (SORTN - 1);
    if (i >= ANCH) { g_keys[t] = ~0ULL; return; }

    float4 an = g_anchor4[i];
    const float* lp = out + OUT_LOC + ((size_t)b * ANCH + i) * 4;
    float l0 = lp[0], l1 = lp[1], l2 = lp[2], l3 = lp[3];

    float aw = an.z - an.x, ah = an.w - an.y;
    float ax = an.x + 0.5f * aw, ay = an.y + 0.5f * ah;
    float cx = l0 * aw + ax;
    float cy = l1 * ah + ay;
    float w  = expf(l2) * aw;
    float h  = expf(l3) * ah;
    float imw = read_dim(pw), imh = read_dim(ph);
    float x0 = fminf(fmaxf(cx - 0.5f * w, 0.f), imw);
    float y0 = fminf(fmaxf(cy - 0.5f * h, 0.f), imh);
    float x1 = fminf(fmaxf(cx + 0.5f * w, 0.f), imw);
    float y1 = fminf(fmaxf(cy + 0.5f * h, 0.f), imh);

    bool valid = ((x1 - x0) >= 16.f) && ((y1 - y0) >= 16.f);
    float sc = valid ? g_fg[(size_t)b * ANCH + i] : __int_as_float(0xff800000);

    g_boxes[(size_t)b * ANCH + i] = make_float4(x0, y0, x1, y1);

    unsigned sbits = __float_as_uint(sc);
    unsigned ord   = (sbits & 0x80000000u) ? ~sbits : (sbits | 0x80000000u);
    unsigned hi    = ~ord;
    g_keys[t] = ((unsigned long long)hi << 32) | (unsigned)i;
}

// ---------------- staged bitonic sort ----------------
__global__ void sort8k_k()
{
    extern __shared__ unsigned long long sk[];
    const int tid = threadIdx.x;
    const size_t base = (size_t)blockIdx.x * 8192;
#pragma unroll
    for (int r = 0; r < 8; r++) sk[tid + r * 1024] = g_keys[base + tid + r * 1024];
    __syncthreads();
    const unsigned gb = (unsigned)(base & (SORTN - 1));
    for (int len = 2; len <= 8192; len <<= 1) {
        for (int s = len >> 1; s > 0; s >>= 1) {
            for (int t = tid; t < 4096; t += 1024) {
                int i = 2 * t - (t & (s - 1));
                int j = i + s;
                bool asc = (((gb + i) & len) == 0);
                unsigned long long a = sk[i], b = sk[j];
                if ((a > b) == asc) { sk[i] = b; sk[j] = a; }
            }
            __syncthreads();
        }
    }
#pragma unroll
    for (int r = 0; r < 8; r++) g_keys[base + tid + r * 1024] = sk[tid + r * 1024];
}

__global__ void gpass_k(int len, int s)
{
    int t = blockIdx.x * 256 + threadIdx.x;
    int b = t >> 15;
    int tt = t & 32767;
    int i = 2 * tt - (tt & (s - 1));
    int j = i + s;
    bool asc = ((i & len) == 0);
    unsigned long long* k = g_keys + (size_t)b * SORTN;
    unsigned long long a = k[i], c = k[j];
    if ((a > c) == asc) { k[i] = c; k[j] = a; }
}

__global__ void tail_k(int len)
{
    extern __shared__ unsigned long long sk[];
    const int tid = threadIdx.x;
    const size_t base = (size_t)blockIdx.x * 8192;
#pragma unroll
    for (int r = 0; r < 8; r++) sk[tid + r * 1024] = g_keys[base + tid + r * 1024];
    __syncthreads();
    const bool asc = (((unsigned)(base & (SORTN - 1)) & (unsigned)len) == 0);
    for (int s = 4096; s > 0; s >>= 1) {
        for (int t = tid; t < 4096; t += 1024) {
            int i = 2 * t - (t & (s - 1));
            int j = i + s;
            unsigned long long a = sk[i], b = sk[j];
            if ((a > b) == asc) { sk[i] = b; sk[j] = a; }
        }
        __syncthreads();
    }
#pragma unroll
    for (int r = 0; r < 8; r++) g_keys[base + tid + r * 1024] = sk[tid + r * 1024];
}

// ---------------- NMS: gather sorted boxes ----------------
__global__ void gather_k()
{
    int b = blockIdx.x;
    int j = blockIdx.y * 1024 + threadIdx.x;
    if (j >= PRE_NMS) return;
    unsigned long long key = g_keys[(size_t)b * SORTN + j];
    unsigned idx = (unsigned)key;
    unsigned hi  = (unsigned)(key >> 32);
    float4 bx = g_boxes[(size_t)b * ANCH + idx];
    g_sbox[b][j]  = bx;
    g_sarea[b][j] = (bx.z - bx.x) * (bx.w - bx.y);
    if (hi >> 31) atomicOr(&g_rminit[b][j >> 6], 1ULL << (j & 63));
}

// ---------------- NMS: suppression mask matrix ----------------
__global__ __launch_bounds__(256) void mask_k()
{
    __shared__ float4 sjb[512];
    __shared__ float  sja[512];
    int b     = blockIdx.z;
    int jbase = blockIdx.x * 512;
    int i     = blockIdx.y * 32 + (threadIdx.x & 31);
    int w     = (jbase >> 6) + (threadIdx.x >> 5);

    for (int t = threadIdx.x; t < 512; t += 256) {
        int j = jbase + t;
        if (j < PRE_NMS) { sjb[t] = g_sbox[b][j]; sja[t] = g_sarea[b][j]; }
        else             { sjb[t] = make_float4(0, 0, 0, 0); sja[t] = 0.f; }
    }
    __syncthreads();
    if (i >= PRE_NMS) return;

    float4 bi = g_sbox[b][i];
    float  ai = g_sarea[b][i];
    unsigned long long bits = 0;
    if (w * 64 + 63 > i) {
        int tj0 = w * 64 - jbase;
#pragma unroll 8
        for (int bit = 0; bit < 64; bit++) {
            int j = w * 64 + bit;
            if (j > i && j < PRE_NMS) {
                float4 bj = sjb[tj0 + bit];
                float xx1 = fmaxf(bi.x, bj.x);
                float yy1 = fmaxf(bi.y, bj.y);
                float xx2 = fminf(bi.z, bj.z);
                float yy2 = fminf(bi.w, bj.w);
                float iw = fmaxf(xx2 - xx1, 0.f);
                float ih = fmaxf(yy2 - yy1, 0.f);
                float inter = iw * ih;
                float iou = inter / (ai + sja[tj0 + bit] - inter + 1e-9f);
                if (iou > NMS_TH) bits |= 1ULL << bit;
            }
        }
    }
    g_mask[b][i][w] = bits;
}

// ---------------- NMS: warp-sequential reduce with early exit ----------------
__global__ void reduce_k(float* __restrict__ out)
{
    int b = blockIdx.x, lane = threadIdx.x;
    unsigned long long rm0 = g_rminit[b][lane];
    unsigned long long rm1 = g_rminit[b][lane + 32];
    unsigned long long rm2 = g_rminit[b][lane + 64];

    float* outroi = out + OUT_ROI + (size_t)b * POST_NMS * 4;
    for (int r = lane; r < POST_NMS * 4; r += 32) outroi[r] = 0.f;
    __syncwarp();

    int kc = 0;
    for (int i = 0; i < PRE_NMS; i++) {
        int w = i >> 6, slot = w >> 5, owner = w & 31;
        unsigned long long mine = (slot == 0) ? rm0 : ((slot == 1) ? rm1 : rm2);
        unsigned long long wv = __shfl_sync(0xffffffffu, mine, owner);
        if (!((wv >> (i & 63)) & 1ULL)) {
            if (lane < 4)
                outroi[kc * 4 + lane] = ((const float*)&g_sbox[b][i])[lane];
            kc++;
            if (kc == POST_NMS) break;
            const unsigned long long* mrow = g_mask[b][i];
            rm0 |= mrow[lane];
            rm1 |= mrow[lane + 32];
            rm2 |= mrow[lane + 64];
        }
    }
}

// ---------------- launch ----------------
extern "C" void kernel_launch(void* const* d_in, const int* in_sizes, int n_in,
                              void* d_out, int out_size)
{
    const float* x   = (const float*)d_in[0];
    const float* c1w = (const float*)d_in[1];
    const float* c1b = (const float*)d_in[2];
    const float* sw  = (const float*)d_in[3];
    const float* sb  = (const float*)d_in[4];
    const float* lw  = (const float*)d_in[5];
    const float* lb  = (const float*)d_in[6];
    const int*   ih  = (const int*)d_in[7];
    const int*   iw  = (const int*)d_in[8];
    float* out = (float*)d_out;

    cudaFuncSetAttribute(sort8k_k,    cudaFuncAttributeMaxDynamicSharedMemorySize, 65536);
    cudaFuncSetAttribute(tail_k,      cudaFuncAttributeMaxDynamicSharedMemorySize, 65536);
    cudaFuncSetAttribute(hmma_gemm_k, cudaFuncAttributeMaxDynamicSharedMemorySize, 2 * STG);

    asplit_k<<<(OC * CIN + 255) / 256, 256>>>(c1w);
    tsplit_k<<<dim3((HW + 31) / 32, CIN / 32, BATCH), 256>>>(x);
    hmma_gemm_k<<<dim3(238, 4), 256, 2 * STG>>>(c1b);
    head_k<<<(NPIX + 127) / 128, 128>>>(lw, lb, sw, sb, out);
    anchor_k<<<(ANCH + 255) / 256, 256>>>(out);
    boxes_k<<<(BATCH * SORTN) / 256, 256>>>(out, ih, iw);

    sort8k_k<<<64, 1024, 65536>>>();
    gpass_k<<<1024, 256>>>(16384, 8192);
    tail_k<<<64, 1024, 65536>>>(16384);
    gpass_k<<<1024, 256>>>(32768, 16384);
    gpass_k<<<1024, 256>>>(32768, 8192);
    tail_k<<<64, 1024, 65536>>>(32768);
    gpass_k<<<1024, 256>>>(65536, 32768);
    gpass_k<<<1024, 256>>>(65536, 16384);
    gpass_k<<<1024, 256>>>(65536, 8192);
    tail_k<<<64, 1024, 65536>>>(65536);

    gather_k<<<dim3(8, 6), 1024>>>();
    mask_k<<<dim3(12, 188, 8), 256>>>();
    reduce_k<<<8, 32>>>(out);
}